// round 5
// baseline (speedup 1.0000x reference)
#include <cuda_runtime.h>
#include <math.h>
#include <stdint.h>

#define BB 16384

// ---------------- device scratch (static, no allocation) ----------------
__device__ float g_Wcat[128 * 1280];            // [128][1024 MQK | 256 Wres]
__device__ float g_PR[(size_t)BB * 1280];       // per-row: P(1024) | R(256)
__device__ float g_U[(size_t)BB * 1024];        // u per head (4 x 256)
__device__ float g_Z1[(size_t)BB * 256];
__device__ float g_H1[(size_t)BB * 256];

// ---------------- helpers ----------------
__device__ __forceinline__ float wsum(float v) {
#pragma unroll
  for (int o = 16; o; o >>= 1) v += __shfl_xor_sync(0xffffffffu, v, o);
  return v;
}
__device__ __forceinline__ float wmax(float v) {
#pragma unroll
  for (int o = 16; o; o >>= 1) v = fmaxf(v, __shfl_xor_sync(0xffffffffu, v, o));
  return v;
}

// packed f32x2 FMA: d = a*b + d (elementwise on 2 floats)
#define FMA2(d, a, b) \
  asm("fma.rn.f32x2 %0, %1, %2, %0;" : "+l"(d) : "l"(a), "l"(b))

__device__ __forceinline__ unsigned long long dup2(float x) {
  unsigned long long r;
  asm("mov.b64 %0, {%1, %1};" : "=l"(r) : "f"(x));
  return r;
}
__device__ __forceinline__ float2 unpk(unsigned long long p) {
  float2 r;
  asm("mov.b64 {%0, %1}, %2;" : "=f"(r.x), "=f"(r.y) : "l"(p));
  return r;
}

// FMA-pipe sincos (avoid MUFU.SIN throughput wall). Valid for |z| <~ 1e4.
__device__ __forceinline__ void fast_sincos(float z, float& s, float& c) {
  float t = rintf(z * 0.63661977236758134f);  // 2/pi
  int qi = (int)t;
  float r = fmaf(t, -1.5703125f, z);
  r = fmaf(t, -4.83751296997070312e-4f, r);
  r = fmaf(t, -7.54978995489188e-8f, r);
  float r2 = r * r;
  float sp = fmaf(r2, -1.9515296e-4f, 8.3321608e-3f);
  sp = fmaf(r2, sp, -1.6666654611e-1f);
  float sinr = fmaf(r * r2, sp, r);
  float cp = fmaf(r2, -1.388731625493765e-3f, 4.166664568298827e-2f);
  cp = fmaf(r2, cp, -0.5f);
  float cosr = fmaf(r2, cp, 1.0f);
  int qq = qi & 3;
  float ss = (qq & 1) ? cosr : sinr;
  float cc = (qq & 1) ? sinr : cosr;
  s = (qq & 2) ? -ss : ss;
  c = ((qq + 1) & 2) ? -cc : cc;
}

// ---------------- K0: MQK_h[i][j] = sum_d Wq[i,64h+d]*Wk[j,64h+d] ----------------
__global__ void __launch_bounds__(256) mqk_kernel(const float* __restrict__ Wq,
                                                  const float* __restrict__ Wk) {
  __shared__ float sWq[16 * 68];
  __shared__ float sWk[128 * 68];
  int h = blockIdx.x, is = blockIdx.y;
  int tid = threadIdx.x;
  {
    int il = tid >> 4, d4 = tid & 15;
    *(float4*)&sWq[il * 68 + d4 * 4] =
        *(const float4*)&Wq[(size_t)(is * 16 + il) * 256 + h * 64 + d4 * 4];
  }
  for (int jc = 0; jc < 2; jc++) {
    __syncthreads();
#pragma unroll
    for (int it = 0; it < 8; it++) {
      int f = tid + it * 256;
      int j = f >> 4, d4 = f & 15;
      *(float4*)&sWk[j * 68 + d4 * 4] =
          *(const float4*)&Wk[(size_t)(jc * 128 + j) * 256 + h * 64 + d4 * 4];
    }
    __syncthreads();
    int j = tid & 127, ih = tid >> 7;
#pragma unroll 1
    for (int il = ih * 8; il < ih * 8 + 8; il++) {
      float acc = 0.f;
#pragma unroll
      for (int d = 0; d < 64; d++) acc = fmaf(sWq[il * 68 + d], sWk[j * 68 + d], acc);
      g_Wcat[(size_t)(is * 16 + il) * 1280 + h * 256 + jc * 128 + j] = acc;
    }
  }
}

__global__ void copy_wres_kernel(const float* __restrict__ Wres) {
  int i = blockIdx.x, tid = threadIdx.x;
  g_Wcat[(size_t)i * 1280 + 1024 + tid] = Wres[(size_t)i * 256 + tid];
}

// ---------------- double-buffered SIMT GEMM (FMA2), BM=64 BN=256 BK=32 --------------
// EPI: 0 = plain store, 1 = relu(x+bias), 2 = LN(x+bias+resid)*gamma+beta (gridDim.x==1)
template <int EPI>
__global__ void __launch_bounds__(256, 1) gemm_epi(
    const float* __restrict__ A, const float* __restrict__ W, float* __restrict__ C,
    int K, int ldw, int ldc,
    const float* __restrict__ bias,
    const float* __restrict__ resid, int ldres,
    const float* __restrict__ gamma, const float* __restrict__ beta) {
  extern __shared__ float smdyn[];
  float* sA = smdyn;                 // [2][64*36]
  float* sB = smdyn + 2 * 64 * 36;   // [2][32*256]
  int tid = threadIdx.x;
  int m0 = blockIdx.y * 64, n0 = blockIdx.x * 256;
  int r0 = (tid >> 5) * 8, c0 = (tid & 31) * 8;
  unsigned long long accP[8][4];
#pragma unroll
  for (int i = 0; i < 8; i++)
#pragma unroll
    for (int j = 0; j < 4; j++) accP[i][j] = 0ull;

  float4 aR[2], bR[8];
  int kt_n = K >> 5;

  // prologue: load tile 0
#pragma unroll
  for (int it = 0; it < 2; it++) {
    int f = tid + it * 256, r = f >> 3, kq = f & 7;
    aR[it] = *(const float4*)&A[(size_t)(m0 + r) * K + kq * 4];
  }
#pragma unroll
  for (int it = 0; it < 8; it++) {
    int f = tid + it * 256, kk = f >> 6, c4 = f & 63;
    bR[it] = *(const float4*)&W[(size_t)kk * ldw + n0 + c4 * 4];
  }
#pragma unroll
  for (int it = 0; it < 2; it++) {
    int f = tid + it * 256, r = f >> 3, kq = f & 7;
    *(float4*)&sA[r * 36 + kq * 4] = aR[it];
  }
#pragma unroll
  for (int it = 0; it < 8; it++) {
    int f = tid + it * 256, kk = f >> 6, c4 = f & 63;
    *(float4*)&sB[kk * 256 + c4 * 4] = bR[it];
  }
  __syncthreads();

  for (int kt = 0; kt < kt_n; kt++) {
    // prefetch next tile into regs (overlaps with compute below)
    if (kt + 1 < kt_n) {
#pragma unroll
      for (int it = 0; it < 2; it++) {
        int f = tid + it * 256, r = f >> 3, kq = f & 7;
        aR[it] = *(const float4*)&A[(size_t)(m0 + r) * K + (kt + 1) * 32 + kq * 4];
      }
#pragma unroll
      for (int it = 0; it < 8; it++) {
        int f = tid + it * 256, kk = f >> 6, c4 = f & 63;
        bR[it] = *(const float4*)&W[(size_t)((kt + 1) * 32 + kk) * ldw + n0 + c4 * 4];
      }
    }
    // compute current tile
    const float* cA = sA + (kt & 1) * 64 * 36;
    const float* cB = sB + (kt & 1) * 32 * 256;
#pragma unroll
    for (int kk = 0; kk < 32; kk++) {
      ulonglong2 q0 = *(const ulonglong2*)&cB[kk * 256 + c0];
      ulonglong2 q1 = *(const ulonglong2*)&cB[kk * 256 + c0 + 4];
      unsigned long long bP[4] = {q0.x, q0.y, q1.x, q1.y};
#pragma unroll
      for (int i = 0; i < 8; i++) {
        unsigned long long aD = dup2(cA[(r0 + i) * 36 + kk]);
        FMA2(accP[i][0], aD, bP[0]);
        FMA2(accP[i][1], aD, bP[1]);
        FMA2(accP[i][2], aD, bP[2]);
        FMA2(accP[i][3], aD, bP[3]);
      }
    }
    // store next tile
    if (kt + 1 < kt_n) {
      float* nA = sA + ((kt + 1) & 1) * 64 * 36;
      float* nB = sB + ((kt + 1) & 1) * 32 * 256;
#pragma unroll
      for (int it = 0; it < 2; it++) {
        int f = tid + it * 256, r = f >> 3, kq = f & 7;
        *(float4*)&nA[r * 36 + kq * 4] = aR[it];
      }
#pragma unroll
      for (int it = 0; it < 8; it++) {
        int f = tid + it * 256, kk = f >> 6, c4 = f & 63;
        *(float4*)&nB[kk * 256 + c4 * 4] = bR[it];
      }
      __syncthreads();
    }
  }
  // ---- epilogue ----
  float bb[8], gg[8], ee[8];
  if (EPI >= 1) {
#pragma unroll
    for (int j = 0; j < 8; j++) bb[j] = bias[n0 + c0 + j];
  }
  if (EPI == 2) {
#pragma unroll
    for (int j = 0; j < 8; j++) {
      gg[j] = gamma[n0 + c0 + j];
      ee[j] = beta[n0 + c0 + j];
    }
  }
#pragma unroll
  for (int i = 0; i < 8; i++) {
    size_t row = (size_t)(m0 + r0 + i);
    float v[8];
#pragma unroll
    for (int j2 = 0; j2 < 4; j2++) {
      float2 u = unpk(accP[i][j2]);
      v[2 * j2] = u.x;
      v[2 * j2 + 1] = u.y;
    }
    if (EPI == 1) {
#pragma unroll
      for (int j = 0; j < 8; j++) v[j] = fmaxf(v[j] + bb[j], 0.f);
    } else if (EPI == 2) {
      float4 rr0 = *(const float4*)&resid[row * ldres + c0];
      float4 rr1 = *(const float4*)&resid[row * ldres + c0 + 4];
      float rj[8] = {rr0.x, rr0.y, rr0.z, rr0.w, rr1.x, rr1.y, rr1.z, rr1.w};
#pragma unroll
      for (int j = 0; j < 8; j++) v[j] = v[j] + bb[j] + rj[j];
      float s = 0.f;
#pragma unroll
      for (int j = 0; j < 8; j++) s += v[j];
      s = wsum(s);
      float mean = s * (1.f / 256.f);
      float q = 0.f;
#pragma unroll
      for (int j = 0; j < 8; j++) {
        float d = v[j] - mean;
        q += d * d;
      }
      q = wsum(q);
      float rstd = rsqrtf(q * (1.f / 256.f) + 1e-5f);
#pragma unroll
      for (int j = 0; j < 8; j++) v[j] = (v[j] - mean) * rstd * gg[j] + ee[j];
    }
    float4 o0 = {v[0], v[1], v[2], v[3]};
    float4 o1 = {v[4], v[5], v[6], v[7]};
    *(float4*)&C[row * ldc + n0 + c0] = o0;
    *(float4*)&C[row * ldc + n0 + c0 + 4] = o1;
  }
}

// ---------------- K2: attention -> u (conflict-free smem, shuffled weights) --------
__global__ void __launch_bounds__(256) attn_u_kernel(
    const float* __restrict__ x_ctx, const float* __restrict__ t_ctx,
    const float* __restrict__ freq, const float* __restrict__ phase) {
  __shared__ float kv[32 * 260];
  __shared__ float p2[4 * 8 * 36];
  __shared__ float slog[128];
  __shared__ float sw[128];
  __shared__ float sfr[64], sph[64];
  int b = blockIdx.x, tid = threadIdx.x;
  int l = tid >> 3, sub = tid & 7;
  int lane = tid & 31;

  if (tid < 64) {
    sfr[tid] = freq[tid];
    sph[tid] = phase[tid];
  }
  // repack p: block (h, s2) holds 8 float4 chunks: c0-3 = x dims s2*16..+15,
  // c4-5 = sin dims 128+s2*8..+7, c6-7 = cos dims 192+s2*8..+7
  {
    int h = tid >> 6, r = tid & 63, s2 = r >> 3, c = r & 7;
    int idx4;
    if (c < 4) idx4 = h * 64 + s2 * 4 + c;
    else if (c < 6) idx4 = h * 64 + 32 + s2 * 2 + (c - 4);
    else idx4 = h * 64 + 48 + s2 * 2 + (c - 6);
    float4 v = *(const float4*)&g_PR[(size_t)b * 1280 + (size_t)idx4 * 4];
    *(float4*)&p2[(h * 8 + s2) * 36 + c * 4] = v;
  }
  __syncthreads();

  float acc[4] = {0.f, 0.f, 0.f, 0.f};
  const float* xsrc = x_ctx + ((size_t)b * 32 + l) * 128 + sub * 16;
  float* kvrow = kv + l * 260;

  // x-part: stream 4 chunks: LDG -> STS -> FMA vs p2
#pragma unroll
  for (int c = 0; c < 4; c++) {
    float4 v = *(const float4*)&xsrc[c * 4];
    *(float4*)&kvrow[sub * 16 + c * 4] = v;
#pragma unroll
    for (int h = 0; h < 4; h++) {
      float4 p = *(const float4*)&p2[(h * 8 + sub) * 36 + c * 4];
      acc[h] = fmaf(v.x, p.x, acc[h]);
      acc[h] = fmaf(v.y, p.y, acc[h]);
      acc[h] = fmaf(v.z, p.z, acc[h]);
      acc[h] = fmaf(v.w, p.w, acc[h]);
    }
  }
  // te-part
  {
    float t = t_ctx[(size_t)b * 32 + l];
    float lt = log1pf(fmaxf(t, 0.f));
#pragma unroll
    for (int g = 0; g < 2; g++) {
      float4 sv, cv;
      float ss, cc;
      int k0 = sub * 8 + g * 4;
      float z0 = fmaf(lt, sfr[k0 + 0], sph[k0 + 0]);
      float z1 = fmaf(lt, sfr[k0 + 1], sph[k0 + 1]);
      float z2 = fmaf(lt, sfr[k0 + 2], sph[k0 + 2]);
      float z3 = fmaf(lt, sfr[k0 + 3], sph[k0 + 3]);
      fast_sincos(z0, ss, cc); sv.x = ss; cv.x = cc;
      fast_sincos(z1, ss, cc); sv.y = ss; cv.y = cc;
      fast_sincos(z2, ss, cc); sv.z = ss; cv.z = cc;
      fast_sincos(z3, ss, cc); sv.w = ss; cv.w = cc;
      *(float4*)&kvrow[128 + sub * 8 + g * 4] = sv;
      *(float4*)&kvrow[192 + sub * 8 + g * 4] = cv;
#pragma unroll
      for (int h = 0; h < 4; h++) {
        float4 ps = *(const float4*)&p2[(h * 8 + sub) * 36 + (4 + g) * 4];
        float4 pc = *(const float4*)&p2[(h * 8 + sub) * 36 + (6 + g) * 4];
        acc[h] = fmaf(sv.x, ps.x, acc[h]);
        acc[h] = fmaf(sv.y, ps.y, acc[h]);
        acc[h] = fmaf(sv.z, ps.z, acc[h]);
        acc[h] = fmaf(sv.w, ps.w, acc[h]);
        acc[h] = fmaf(cv.x, pc.x, acc[h]);
        acc[h] = fmaf(cv.y, pc.y, acc[h]);
        acc[h] = fmaf(cv.z, pc.z, acc[h]);
        acc[h] = fmaf(cv.w, pc.w, acc[h]);
      }
    }
  }
  // reduce over sub (8 lanes)
#pragma unroll
  for (int h = 0; h < 4; h++) {
#pragma unroll
    for (int o = 4; o; o >>= 1) acc[h] += __shfl_xor_sync(0xffffffffu, acc[h], o);
  }
  if (sub < 4) slog[sub * 32 + l] = acc[sub] * 0.125f;
  __syncthreads();
  if (tid < 128) {
    float v = slog[tid];
    float m = wmax(v);
    float e = __expf(v - m);
    float s = wsum(e);
    sw[tid] = e / s;
  }
  __syncthreads();
  // u-phase: thread owns kv-dim j = tid, all 4 heads.
  // softmax weights live in registers, broadcast via shuffle (no LDS traffic).
  {
    float w0 = sw[lane];
    float w1 = sw[32 + lane];
    float w2 = sw[64 + lane];
    float w3 = sw[96 + lane];
    float a0 = 0.f, a1 = 0.f, a2 = 0.f, a3 = 0.f;
#pragma unroll
    for (int ll = 0; ll < 32; ll++) {
      float v = kv[ll * 260 + tid];
      a0 = fmaf(__shfl_sync(0xffffffffu, w0, ll), v, a0);
      a1 = fmaf(__shfl_sync(0xffffffffu, w1, ll), v, a1);
      a2 = fmaf(__shfl_sync(0xffffffffu, w2, ll), v, a2);
      a3 = fmaf(__shfl_sync(0xffffffffu, w3, ll), v, a3);
    }
    size_t o = (size_t)b * 1024 + tid;
    g_U[o] = a0;
    g_U[o + 256] = a1;
    g_U[o + 512] = a2;
    g_U[o + 768] = a3;
  }
}

// ---------------- K3: head-split GEMM agg = u_h @ Wv[:,h*64..] + LN epilogue --------
// BM=64, BN=256 (4 heads x 64), BK=16, double-buffered, grid (1, B/64)
__global__ void __launch_bounds__(256, 1) gemm_hs_ln(
    const float* __restrict__ Wv, float* __restrict__ C,
    const float* __restrict__ bias, const float* __restrict__ resid, int ldres,
    const float* __restrict__ gamma, const float* __restrict__ beta) {
  extern __shared__ float smdyn[];
  float* sA = smdyn;                 // [2][64*80]
  float* sB = smdyn + 2 * 64 * 80;   // [2][16*256]
  int tid = threadIdx.x;
  int m0 = blockIdx.y * 64;
  int r0 = (tid >> 5) * 8, c0 = (tid & 31) * 8, hh = c0 >> 6;
  unsigned long long accP[8][4];
#pragma unroll
  for (int i = 0; i < 8; i++)
#pragma unroll
    for (int j = 0; j < 4; j++) accP[i][j] = 0ull;

  float4 aR[4], bR[4];
  // prologue: load kt=0
#pragma unroll
  for (int it = 0; it < 4; it++) {
    int f = tid + it * 256, r = f >> 4, q = f & 15, h = q >> 2, kq = q & 3;
    aR[it] = *(const float4*)&g_U[(size_t)(m0 + r) * 1024 + h * 256 + kq * 4];
  }
#pragma unroll
  for (int it = 0; it < 4; it++) {
    int f = tid + it * 256, kk = f >> 6, c4 = f & 63;
    bR[it] = *(const float4*)&Wv[(size_t)kk * 256 + c4 * 4];
  }
#pragma unroll
  for (int it = 0; it < 4; it++) {
    int f = tid + it * 256, r = f >> 4, q = f & 15, h = q >> 2, kq = q & 3;
    *(float4*)&sA[r * 80 + h * 20 + kq * 4] = aR[it];
  }
#pragma unroll
  for (int it = 0; it < 4; it++) {
    int f = tid + it * 256, kk = f >> 6, c4 = f & 63;
    *(float4*)&sB[kk * 256 + c4 * 4] = bR[it];
  }
  __syncthreads();

  for (int kt = 0; kt < 16; kt++) {
    if (kt + 1 < 16) {
#pragma unroll
      for (int it = 0; it < 4; it++) {
        int f = tid + it * 256, r = f >> 4, q = f & 15, h = q >> 2, kq = q & 3;
        aR[it] = *(const float4*)&g_U[(size_t)(m0 + r) * 1024 + h * 256 +
                                      (kt + 1) * 16 + kq * 4];
      }
#pragma unroll
      for (int it = 0; it < 4; it++) {
        int f = tid + it * 256, kk = f >> 6, c4 = f & 63;
        bR[it] = *(const float4*)&Wv[(size_t)((kt + 1) * 16 + kk) * 256 + c4 * 4];
      }
    }
    const float* cA = sA + (kt & 1) * 64 * 80;
    const float* cB = sB + (kt & 1) * 16 * 256;
#pragma unroll
    for (int kk = 0; kk < 16; kk++) {
      ulonglong2 q0 = *(const ulonglong2*)&cB[kk * 256 + c0];
      ulonglong2 q1 = *(const ulonglong2*)&cB[kk * 256 + c0 + 4];
      unsigned long long bP[4] = {q0.x, q0.y, q1.x, q1.y};
#pragma unroll
      for (int i = 0; i < 8; i++) {
        unsigned long long aD = dup2(cA[(r0 + i) * 80 + hh * 20 + kk]);
        FMA2(accP[i][0], aD, bP[0]);
        FMA2(accP[i][1], aD, bP[1]);
        FMA2(accP[i][2], aD, bP[2]);
        FMA2(accP[i][3], aD, bP[3]);
      }
    }
    if (kt + 1 < 16) {
      float* nA = sA + ((kt + 1) & 1) * 64 * 80;
      float* nB = sB + ((kt + 1) & 1) * 16 * 256;
#pragma unroll
      for (int it = 0; it < 4; it++) {
        int f = tid + it * 256, r = f >> 4, q = f & 15, h = q >> 2, kq = q & 3;
        *(float4*)&nA[r * 80 + h * 20 + kq * 4] = aR[it];
      }
#pragma unroll
      for (int it = 0; it < 4; it++) {
        int f = tid + it * 256, kk = f >> 6, c4 = f & 63;
        *(float4*)&nB[kk * 256 + c4 * 4] = bR[it];
      }
      __syncthreads();
    }
  }
  // ---- LN epilogue: LN(acc + bias + resid) * gamma + beta ----
  float bb[8], gg[8], ee[8];
#pragma unroll
  for (int j = 0; j < 8; j++) {
    bb[j] = bias[c0 + j];
    gg[j] = gamma[c0 + j];
    ee[j] = beta[c0 + j];
  }
#pragma unroll
  for (int i = 0; i < 8; i++) {
    size_t row = (size_t)(m0 + r0 + i);
    float v[8];
#pragma unroll
    for (int j2 = 0; j2 < 4; j2++) {
      float2 u = unpk(accP[i][j2]);
      v[2 * j2] = u.x;
      v[2 * j2 + 1] = u.y;
    }
    float4 rr0 = *(const float4*)&resid[row * ldres + c0];
    float4 rr1 = *(const float4*)&resid[row * ldres + c0 + 4];
    float rj[8] = {rr0.x, rr0.y, rr0.z, rr0.w, rr1.x, rr1.y, rr1.z, rr1.w};
#pragma unroll
    for (int j = 0; j < 8; j++) v[j] = v[j] + bb[j] + rj[j];
    float s = 0.f;
#pragma unroll
    for (int j = 0; j < 8; j++) s += v[j];
    s = wsum(s);
    float mean = s * (1.f / 256.f);
    float q = 0.f;
#pragma unroll
    for (int j = 0; j < 8; j++) {
      float d = v[j] - mean;
      q += d * d;
    }
    q = wsum(q);
    float rstd = rsqrtf(q * (1.f / 256.f) + 1e-5f);
#pragma unroll
    for (int j = 0; j < 8; j++) v[j] = (v[j] - mean) * rstd * gg[j] + ee[j];
    float4 o0 = {v[0], v[1], v[2], v[3]};
    float4 o1 = {v[4], v[5], v[6], v[7]};
    *(float4*)&C[row * 256 + c0] = o0;
    *(float4*)&C[row * 256 + c0 + 4] = o1;
  }
}

// ---------------- launch ----------------
extern "C" void kernel_launch(void* const* d_in, const int* in_sizes, int n_in,
                              void* d_out, int out_size) {
  const float* x_u   = (const float*)d_in[0];
  const float* x_ctx = (const float*)d_in[1];
  const float* t_ctx = (const float*)d_in[2];
  const float* freq  = (const float*)d_in[3];
  const float* phase = (const float*)d_in[4];
  const float* Wq    = (const float*)d_in[5];
  const float* Wk    = (const float*)d_in[6];
  const float* Wv    = (const float*)d_in[7];
  const float* Wres  = (const float*)d_in[8];
  const float* bres  = (const float*)d_in[9];
  const float* W1    = (const float*)d_in[10];
  const float* b1    = (const float*)d_in[11];
  const float* W2    = (const float*)d_in[12];
  const float* b2    = (const float*)d_in[13];
  const float* g1    = (const float*)d_in[14];
  const float* be1   = (const float*)d_in[15];
  const float* g2    = (const float*)d_in[16];
  const float* be2   = (const float*)d_in[17];
  float* out = (float*)d_out;

  float *pWcat, *pPR, *pU, *pZ1, *pH1;
  cudaGetSymbolAddress((void**)&pWcat, g_Wcat);
  cudaGetSymbolAddress((void**)&pPR, g_PR);
  cudaGetSymbolAddress((void**)&pU, g_U);
  cudaGetSymbolAddress((void**)&pZ1, g_Z1);
  cudaGetSymbolAddress((void**)&pH1, g_H1);

  int smemBig = (2 * 64 * 36 + 2 * 32 * 256) * 4;   // 83,968 B
  int smemHs = (2 * 64 * 80 + 2 * 16 * 256) * 4;    // 73,728 B
  cudaFuncSetAttribute(gemm_epi<0>, cudaFuncAttributeMaxDynamicSharedMemorySize, smemBig);
  cudaFuncSetAttribute(gemm_epi<1>, cudaFuncAttributeMaxDynamicSharedMemorySize, smemBig);
  cudaFuncSetAttribute(gemm_epi<2>, cudaFuncAttributeMaxDynamicSharedMemorySize, smemBig);
  cudaFuncSetAttribute(gemm_hs_ln, cudaFuncAttributeMaxDynamicSharedMemorySize, smemHs);

  // K0: build [MQK | Wres]
  mqk_kernel<<<dim3(4, 8), 256>>>(Wq, Wk);
  copy_wres_kernel<<<128, 256>>>(Wres);

  // K1: P|R = x_u @ Wcat   [16384,128] x [128,1280]
  gemm_epi<0><<<dim3(5, 256), 256, smemBig>>>(x_u, pWcat, pPR, 128, 1280, 1280,
                                              nullptr, nullptr, 0, nullptr, nullptr);

  // K2: attention -> u
  attn_u_kernel<<<BB, 256>>>(x_ctx, t_ctx, freq, phase);

  // K3: z1 = LN(u_h @ Wv_h + R + bres)
  gemm_hs_ln<<<dim3(1, 256), 256, smemHs>>>(Wv, pZ1, bres, pPR + 1024, 1280, g1, be1);

  // K4: h1 = relu(z1 @ W1 + b1)
  gemm_epi<1><<<dim3(1, 256), 256, smemBig>>>(pZ1, W1, pH1, 256, 256, 256,
                                              b1, nullptr, 0, nullptr, nullptr);

  // K5: out = LN(h1 @ W2 + b2 + z1)
  gemm_epi<2><<<dim3(1, 256), 256, smemBig>>>(pH1, W2, out, 256, 256, 256,
                                              b2, pZ1, 256, g2, be2);
}

// round 6
// speedup vs baseline: 1.1266x; 1.1266x over previous
#include <cuda_runtime.h>
#include <math.h>
#include <stdint.h>

#define BB 16384

// ---------------- device scratch (static, no allocation) ----------------
__device__ float g_Wcat[128 * 1280];            // [128][1024 MQK | 256 Wres]
__device__ float g_PR[(size_t)BB * 1280];       // per-row: P(1024) | R(256)
__device__ float g_U[(size_t)BB * 1024];        // u per head (4 x 256)
__device__ float g_S[(size_t)BB * 256];         // pre-LN scratch
__device__ float g_Z1[(size_t)BB * 256];
__device__ float g_H1[(size_t)BB * 256];

// ---------------- helpers ----------------
__device__ __forceinline__ float wsum(float v) {
#pragma unroll
  for (int o = 16; o; o >>= 1) v += __shfl_xor_sync(0xffffffffu, v, o);
  return v;
}
__device__ __forceinline__ float wmax(float v) {
#pragma unroll
  for (int o = 16; o; o >>= 1) v = fmaxf(v, __shfl_xor_sync(0xffffffffu, v, o));
  return v;
}

// packed f32x2 FMA: d = a*b + d (elementwise on 2 floats)
#define FMA2(d, a, b) \
  asm("fma.rn.f32x2 %0, %1, %2, %0;" : "+l"(d) : "l"(a), "l"(b))

__device__ __forceinline__ unsigned long long dup2(float x) {
  unsigned long long r;
  asm("mov.b64 %0, {%1, %1};" : "=l"(r) : "f"(x));
  return r;
}
__device__ __forceinline__ float2 unpk(unsigned long long p) {
  float2 r;
  asm("mov.b64 {%0, %1}, %2;" : "=f"(r.x), "=f"(r.y) : "l"(p));
  return r;
}

// FMA-pipe sincos (avoid MUFU.SIN throughput wall). Valid for |z| <~ 1e4.
__device__ __forceinline__ void fast_sincos(float z, float& s, float& c) {
  float t = rintf(z * 0.63661977236758134f);  // 2/pi
  int qi = (int)t;
  float r = fmaf(t, -1.5703125f, z);
  r = fmaf(t, -4.83751296997070312e-4f, r);
  r = fmaf(t, -7.54978995489188e-8f, r);
  float r2 = r * r;
  float sp = fmaf(r2, -1.9515296e-4f, 8.3321608e-3f);
  sp = fmaf(r2, sp, -1.6666654611e-1f);
  float sinr = fmaf(r * r2, sp, r);
  float cp = fmaf(r2, -1.388731625493765e-3f, 4.166664568298827e-2f);
  cp = fmaf(r2, cp, -0.5f);
  float cosr = fmaf(r2, cp, 1.0f);
  int qq = qi & 3;
  float ss = (qq & 1) ? cosr : sinr;
  float cc = (qq & 1) ? sinr : cosr;
  s = (qq & 2) ? -ss : ss;
  c = ((qq + 1) & 2) ? -cc : cc;
}

// ---------------- K0: MQK_h[i][j] = sum_d Wq[i,64h+d]*Wk[j,64h+d] ----------------
__global__ void __launch_bounds__(256) mqk_kernel(const float* __restrict__ Wq,
                                                  const float* __restrict__ Wk) {
  __shared__ float sWq[16 * 68];
  __shared__ float sWk[128 * 68];
  int h = blockIdx.x, is = blockIdx.y;
  int tid = threadIdx.x;
  {
    int il = tid >> 4, d4 = tid & 15;
    *(float4*)&sWq[il * 68 + d4 * 4] =
        *(const float4*)&Wq[(size_t)(is * 16 + il) * 256 + h * 64 + d4 * 4];
  }
  for (int jc = 0; jc < 2; jc++) {
    __syncthreads();
#pragma unroll
    for (int it = 0; it < 8; it++) {
      int f = tid + it * 256;
      int j = f >> 4, d4 = f & 15;
      *(float4*)&sWk[j * 68 + d4 * 4] =
          *(const float4*)&Wk[(size_t)(jc * 128 + j) * 256 + h * 64 + d4 * 4];
    }
    __syncthreads();
    int j = tid & 127, ih = tid >> 7;
#pragma unroll 1
    for (int il = ih * 8; il < ih * 8 + 8; il++) {
      float acc = 0.f;
#pragma unroll
      for (int d = 0; d < 64; d++) acc = fmaf(sWq[il * 68 + d], sWk[j * 68 + d], acc);
      g_Wcat[(size_t)(is * 16 + il) * 1280 + h * 256 + jc * 128 + j] = acc;
    }
  }
}

__global__ void copy_wres_kernel(const float* __restrict__ Wres) {
  int i = blockIdx.x, tid = threadIdx.x;
  g_Wcat[(size_t)i * 1280 + 1024 + tid] = Wres[(size_t)i * 256 + tid];
}

// ---------------- SIMT GEMM, warp tile 16x128, A^T smem, FMA2 ----------------
// BM=64 BN=256 BK=32, 256 threads. EPI: 0 = store, 1 = relu(x+bias).
template <int EPI>
__global__ void __launch_bounds__(256, 2) gemm_epi(
    const float* __restrict__ A, const float* __restrict__ W, float* __restrict__ C,
    int K, int ldw, int ldc, const float* __restrict__ bias) {
  __shared__ float sAT[32 * 68];   // [kk][row], padded
  __shared__ float sB[32 * 256];
  int tid = threadIdx.x, lane = tid & 31, wid = tid >> 5;
  int rbase = (wid >> 1) * 16;
  int cb = (wid & 1) * 128 + lane * 4;
  int m0 = blockIdx.y * 64, n0 = blockIdx.x * 256;
  unsigned long long acc[16][2];
#pragma unroll
  for (int i = 0; i < 16; i++) { acc[i][0] = 0ull; acc[i][1] = 0ull; }

  int kt_n = K >> 5;
  for (int kt = 0; kt < kt_n; kt++) {
    __syncthreads();
#pragma unroll
    for (int it = 0; it < 2; it++) {
      int f = tid + it * 256, r = f >> 3, kq = f & 7;
      float4 v = *(const float4*)&A[(size_t)(m0 + r) * K + kt * 32 + kq * 4];
      sAT[(kq * 4 + 0) * 68 + r] = v.x;
      sAT[(kq * 4 + 1) * 68 + r] = v.y;
      sAT[(kq * 4 + 2) * 68 + r] = v.z;
      sAT[(kq * 4 + 3) * 68 + r] = v.w;
    }
#pragma unroll
    for (int it = 0; it < 8; it++) {
      int f = tid + it * 256, kk = f >> 6, c4 = f & 63;
      *(float4*)&sB[kk * 256 + c4 * 4] =
          *(const float4*)&W[(size_t)(kt * 32 + kk) * ldw + n0 + c4 * 4];
    }
    __syncthreads();
#pragma unroll
    for (int kk = 0; kk < 32; kk++) {
      ulonglong2 bq = *(const ulonglong2*)&sB[kk * 256 + cb];
      float4 a0 = *(const float4*)&sAT[kk * 68 + rbase];
      float4 a1 = *(const float4*)&sAT[kk * 68 + rbase + 4];
      float4 a2 = *(const float4*)&sAT[kk * 68 + rbase + 8];
      float4 a3 = *(const float4*)&sAT[kk * 68 + rbase + 12];
      float av[16] = {a0.x, a0.y, a0.z, a0.w, a1.x, a1.y, a1.z, a1.w,
                      a2.x, a2.y, a2.z, a2.w, a3.x, a3.y, a3.z, a3.w};
#pragma unroll
      for (int i = 0; i < 16; i++) {
        unsigned long long d = dup2(av[i]);
        FMA2(acc[i][0], d, bq.x);
        FMA2(acc[i][1], d, bq.y);
      }
    }
  }
  // ---- epilogue ----
  float bb[4];
  if (EPI == 1) {
    float4 bv = *(const float4*)&bias[n0 + cb];
    bb[0] = bv.x; bb[1] = bv.y; bb[2] = bv.z; bb[3] = bv.w;
  }
#pragma unroll
  for (int i = 0; i < 16; i++) {
    float2 u0 = unpk(acc[i][0]);
    float2 u1 = unpk(acc[i][1]);
    float4 o = {u0.x, u0.y, u1.x, u1.y};
    if (EPI == 1) {
      o.x = fmaxf(o.x + bb[0], 0.f);
      o.y = fmaxf(o.y + bb[1], 0.f);
      o.z = fmaxf(o.z + bb[2], 0.f);
      o.w = fmaxf(o.w + bb[3], 0.f);
    }
    *(float4*)&C[(size_t)(m0 + rbase + i) * ldc + n0 + cb] = o;
  }
}

// ---------------- K3: head-split GEMM S = u_h @ Wv[:,h*64..] ----------------
// BM=64, BN=256 (4 heads x 64), BK=16, warp tile 16x128, A^T smem per head.
__global__ void __launch_bounds__(256, 2) gemm_hs(
    const float* __restrict__ Wv, float* __restrict__ C) {
  __shared__ float sAT[16 * 4 * 68];   // [kk][h][row]
  __shared__ float sB[16 * 256];
  int tid = threadIdx.x, lane = tid & 31, wid = tid >> 5;
  int rbase = (wid >> 1) * 16;
  int colslab = wid & 1;
  int cb = colslab * 128 + lane * 4;
  int hl = colslab * 2 + (lane >> 4);
  int m0 = blockIdx.y * 64;
  unsigned long long acc[16][2];
#pragma unroll
  for (int i = 0; i < 16; i++) { acc[i][0] = 0ull; acc[i][1] = 0ull; }

  for (int kt = 0; kt < 16; kt++) {
    __syncthreads();
#pragma unroll
    for (int it = 0; it < 4; it++) {
      int f = tid + it * 256;        // 0..1023
      int r = f >> 4, q = f & 15, h = q >> 2, kq = q & 3;
      float4 v = *(const float4*)&g_U[(size_t)(m0 + r) * 1024 + h * 256 +
                                      kt * 16 + kq * 4];
      sAT[((kq * 4 + 0) * 4 + h) * 68 + r] = v.x;
      sAT[((kq * 4 + 1) * 4 + h) * 68 + r] = v.y;
      sAT[((kq * 4 + 2) * 4 + h) * 68 + r] = v.z;
      sAT[((kq * 4 + 3) * 4 + h) * 68 + r] = v.w;
    }
#pragma unroll
    for (int it = 0; it < 4; it++) {
      int f = tid + it * 256, kk = f >> 6, c4 = f & 63;
      *(float4*)&sB[kk * 256 + c4 * 4] =
          *(const float4*)&Wv[(size_t)(kt * 16 + kk) * 256 + c4 * 4];
    }
    __syncthreads();
#pragma unroll
    for (int kk = 0; kk < 16; kk++) {
      ulonglong2 bq = *(const ulonglong2*)&sB[kk * 256 + cb];
      int ab = (kk * 4 + hl) * 68 + rbase;
      float4 a0 = *(const float4*)&sAT[ab];
      float4 a1 = *(const float4*)&sAT[ab + 4];
      float4 a2 = *(const float4*)&sAT[ab + 8];
      float4 a3 = *(const float4*)&sAT[ab + 12];
      float av[16] = {a0.x, a0.y, a0.z, a0.w, a1.x, a1.y, a1.z, a1.w,
                      a2.x, a2.y, a2.z, a2.w, a3.x, a3.y, a3.z, a3.w};
#pragma unroll
      for (int i = 0; i < 16; i++) {
        unsigned long long d = dup2(av[i]);
        FMA2(acc[i][0], d, bq.x);
        FMA2(acc[i][1], d, bq.y);
      }
    }
  }
#pragma unroll
  for (int i = 0; i < 16; i++) {
    float2 u0 = unpk(acc[i][0]);
    float2 u1 = unpk(acc[i][1]);
    float4 o = {u0.x, u0.y, u1.x, u1.y};
    *(float4*)&C[(size_t)(m0 + rbase + i) * 256 + cb] = o;
  }
}

// ---------------- K2: attention -> u (conflict-free smem, packed sw) ----------
__global__ void __launch_bounds__(256) attn_u_kernel(
    const float* __restrict__ x_ctx, const float* __restrict__ t_ctx,
    const float* __restrict__ freq, const float* __restrict__ phase) {
  __shared__ float kv[32 * 260];
  __shared__ float p2[4 * 8 * 36];
  __shared__ float slog[128];
  __shared__ __align__(16) float sw[128];   // [l][h] packed
  __shared__ float sfr[64], sph[64];
  int b = blockIdx.x, tid = threadIdx.x;
  int l = tid >> 3, sub = tid & 7;

  if (tid < 64) {
    sfr[tid] = freq[tid];
    sph[tid] = phase[tid];
  }
  // repack p: block (h, s2) holds 8 float4 chunks: c0-3 = x dims s2*16..+15,
  // c4-5 = sin dims 128+s2*8..+7, c6-7 = cos dims 192+s2*8..+7
  {
    int h = tid >> 6, r = tid & 63, s2 = r >> 3, c = r & 7;
    int idx4;
    if (c < 4) idx4 = h * 64 + s2 * 4 + c;
    else if (c < 6) idx4 = h * 64 + 32 + s2 * 2 + (c - 4);
    else idx4 = h * 64 + 48 + s2 * 2 + (c - 6);
    float4 v = *(const float4*)&g_PR[(size_t)b * 1280 + (size_t)idx4 * 4];
    *(float4*)&p2[(h * 8 + s2) * 36 + c * 4] = v;
  }
  __syncthreads();

  float acc[4] = {0.f, 0.f, 0.f, 0.f};
  const float* xsrc = x_ctx + ((size_t)b * 32 + l) * 128 + sub * 16;
  float* kvrow = kv + l * 260;

  // x-part: stream 4 chunks: LDG -> STS -> FMA vs p2
#pragma unroll
  for (int c = 0; c < 4; c++) {
    float4 v = *(const float4*)&xsrc[c * 4];
    *(float4*)&kvrow[sub * 16 + c * 4] = v;
#pragma unroll
    for (int h = 0; h < 4; h++) {
      float4 p = *(const float4*)&p2[(h * 8 + sub) * 36 + c * 4];
      acc[h] = fmaf(v.x, p.x, acc[h]);
      acc[h] = fmaf(v.y, p.y, acc[h]);
      acc[h] = fmaf(v.z, p.z, acc[h]);
      acc[h] = fmaf(v.w, p.w, acc[h]);
    }
  }
  // te-part
  {
    float t = t_ctx[(size_t)b * 32 + l];
    float lt = log1pf(fmaxf(t, 0.f));
#pragma unroll
    for (int g = 0; g < 2; g++) {
      float4 sv, cv;
      float ss, cc;
      int k0 = sub * 8 + g * 4;
      float z0 = fmaf(lt, sfr[k0 + 0], sph[k0 + 0]);
      float z1 = fmaf(lt, sfr[k0 + 1], sph[k0 + 1]);
      float z2 = fmaf(lt, sfr[k0 + 2], sph[k0 + 2]);
      float z3 = fmaf(lt, sfr[k0 + 3], sph[k0 + 3]);
      fast_sincos(z0, ss, cc); sv.x = ss; cv.x = cc;
      fast_sincos(z1, ss, cc); sv.y = ss; cv.y = cc;
      fast_sincos(z2, ss, cc); sv.z = ss; cv.z = cc;
      fast_sincos(z3, ss, cc); sv.w = ss; cv.w = cc;
      *(float4*)&kvrow[128 + sub * 8 + g * 4] = sv;
      *(float4*)&kvrow[192 + sub * 8 + g * 4] = cv;
#pragma unroll
      for (int h = 0; h < 4; h++) {
        float4 ps = *(const float4*)&p2[(h * 8 + sub) * 36 + (4 + g) * 4];
        float4 pc = *(const float4*)&p2[(h * 8 + sub) * 36 + (6 + g) * 4];
        acc[h] = fmaf(sv.x, ps.x, acc[h]);
        acc[h] = fmaf(sv.y, ps.y, acc[h]);
        acc[h] = fmaf(sv.z, ps.z, acc[h]);
        acc[h] = fmaf(sv.w, ps.w, acc[h]);
        acc[h] = fmaf(cv.x, pc.x, acc[h]);
        acc[h] = fmaf(cv.y, pc.y, acc[h]);
        acc[h] = fmaf(cv.z, pc.z, acc[h]);
        acc[h] = fmaf(cv.w, pc.w, acc[h]);
      }
    }
  }
  // reduce over sub (8 lanes)
#pragma unroll
  for (int h = 0; h < 4; h++) {
#pragma unroll
    for (int o = 4; o; o >>= 1) acc[h] += __shfl_xor_sync(0xffffffffu, acc[h], o);
  }
  if (sub < 4) slog[sub * 32 + l] = acc[sub] * 0.125f;
  __syncthreads();
  if (tid < 128) {
    int h = tid >> 5, ll = tid & 31;
    float v = slog[tid];
    float m = wmax(v);
    float e = __expf(v - m);
    float s = wsum(e);
    sw[ll * 4 + h] = e / s;   // packed [l][h]
  }
  __syncthreads();
  // u-phase: thread owns kv-dim j = tid, all 4 heads.
  // one 16B broadcast per iteration for all 4 head weights.
  {
    unsigned long long a01 = 0ull, a23 = 0ull;
#pragma unroll
    for (int ll = 0; ll < 32; ll++) {
      ulonglong2 w2 = *(const ulonglong2*)&sw[ll * 4];
      unsigned long long vd = dup2(kv[ll * 260 + tid]);
      FMA2(a01, vd, w2.x);
      FMA2(a23, vd, w2.y);
    }
    float2 u01 = unpk(a01);
    float2 u23 = unpk(a23);
    size_t o = (size_t)b * 1024 + tid;
    g_U[o] = u01.x;
    g_U[o + 256] = u01.y;
    g_U[o + 512] = u23.x;
    g_U[o + 768] = u23.y;
  }
}

// ---------------- LN: out = LN(S + resid + bias)*gamma + beta ----------------
__global__ void __launch_bounds__(256) ln_kernel(
    const float* __restrict__ S, const float* __restrict__ resid, int ldres,
    const float* __restrict__ bias, const float* __restrict__ gamma,
    const float* __restrict__ beta, float* __restrict__ out) {
  int row = blockIdx.x * 8 + (threadIdx.x >> 5);
  int lane = threadIdx.x & 31;
  int c0 = lane * 4, c1 = 128 + lane * 4;
  float4 a0 = *(const float4*)&S[(size_t)row * 256 + c0];
  float4 a1 = *(const float4*)&S[(size_t)row * 256 + c1];
  float4 r0 = *(const float4*)&resid[(size_t)row * ldres + c0];
  float4 r1 = *(const float4*)&resid[(size_t)row * ldres + c1];
  float4 b0 = *(const float4*)&bias[c0];
  float4 b1 = *(const float4*)&bias[c1];
  float v[8];
  v[0] = a0.x + r0.x + b0.x;
  v[1] = a0.y + r0.y + b0.y;
  v[2] = a0.z + r0.z + b0.z;
  v[3] = a0.w + r0.w + b0.w;
  v[4] = a1.x + r1.x + b1.x;
  v[5] = a1.y + r1.y + b1.y;
  v[6] = a1.z + r1.z + b1.z;
  v[7] = a1.w + r1.w + b1.w;
  float s = 0.f;
#pragma unroll
  for (int j = 0; j < 8; j++) s += v[j];
  s = wsum(s);
  float mean = s * (1.f / 256.f);
  float q = 0.f;
#pragma unroll
  for (int j = 0; j < 8; j++) {
    float d = v[j] - mean;
    q += d * d;
  }
  q = wsum(q);
  float rstd = rsqrtf(q * (1.f / 256.f) + 1e-5f);
  float4 g0 = *(const float4*)&gamma[c0];
  float4 g1 = *(const float4*)&gamma[c1];
  float4 e0 = *(const float4*)&beta[c0];
  float4 e1 = *(const float4*)&beta[c1];
  float4 o0, o1;
  o0.x = (v[0] - mean) * rstd * g0.x + e0.x;
  o0.y = (v[1] - mean) * rstd * g0.y + e0.y;
  o0.z = (v[2] - mean) * rstd * g0.z + e0.z;
  o0.w = (v[3] - mean) * rstd * g0.w + e0.w;
  o1.x = (v[4] - mean) * rstd * g1.x + e1.x;
  o1.y = (v[5] - mean) * rstd * g1.y + e1.y;
  o1.z = (v[6] - mean) * rstd * g1.z + e1.z;
  o1.w = (v[7] - mean) * rstd * g1.w + e1.w;
  *(float4*)&out[(size_t)row * 256 + c0] = o0;
  *(float4*)&out[(size_t)row * 256 + c1] = o1;
}

// ---------------- launch ----------------
extern "C" void kernel_launch(void* const* d_in, const int* in_sizes, int n_in,
                              void* d_out, int out_size) {
  const float* x_u   = (const float*)d_in[0];
  const float* x_ctx = (const float*)d_in[1];
  const float* t_ctx = (const float*)d_in[2];
  const float* freq  = (const float*)d_in[3];
  const float* phase = (const float*)d_in[4];
  const float* Wq    = (const float*)d_in[5];
  const float* Wk    = (const float*)d_in[6];
  const float* Wv    = (const float*)d_in[7];
  const float* Wres  = (const float*)d_in[8];
  const float* bres  = (const float*)d_in[9];
  const float* W1    = (const float*)d_in[10];
  const float* b1    = (const float*)d_in[11];
  const float* W2    = (const float*)d_in[12];
  const float* b2    = (const float*)d_in[13];
  const float* g1    = (const float*)d_in[14];
  const float* be1   = (const float*)d_in[15];
  const float* g2    = (const float*)d_in[16];
  const float* be2   = (const float*)d_in[17];
  float* out = (float*)d_out;

  float *pWcat, *pPR, *pS, *pZ1, *pH1;
  cudaGetSymbolAddress((void**)&pWcat, g_Wcat);
  cudaGetSymbolAddress((void**)&pPR, g_PR);
  cudaGetSymbolAddress((void**)&pS, g_S);
  cudaGetSymbolAddress((void**)&pZ1, g_Z1);
  cudaGetSymbolAddress((void**)&pH1, g_H1);

  // K0: build [MQK | Wres]
  mqk_kernel<<<dim3(4, 8), 256>>>(Wq, Wk);
  copy_wres_kernel<<<128, 256>>>(Wres);

  // K1: P|R = x_u @ Wcat   [16384,128] x [128,1280]
  gemm_epi<0><<<dim3(5, 256), 256>>>(x_u, pWcat, pPR, 128, 1280, 1280, nullptr);

  // K2: attention -> u
  attn_u_kernel<<<BB, 256>>>(x_ctx, t_ctx, freq, phase);

  // K3: S = u_h @ Wv_h ; z1 = LN(S + R + bres)
  gemm_hs<<<dim3(1, 256), 256>>>(Wv, pS);
  ln_kernel<<<BB / 8, 256>>>(pS, pPR + 1024, 1280, bres, g1, be1, pZ1);

  // K4: h1 = relu(z1 @ W1 + b1)
  gemm_epi<1><<<dim3(1, 256), 256>>>(pZ1, W1, pH1, 256, 256, 256, b1);

  // K5: S = h1 @ W2 ; out = LN(S + z1 + b2)
  gemm_epi<0><<<dim3(1, 256), 256>>>(pH1, W2, pS, 256, 256, 256, nullptr);
  ln_kernel<<<BB / 8, 256>>>(pS, pZ1, 256, b2, g2, be2, out);
}

// round 7
// speedup vs baseline: 1.2124x; 1.0761x over previous
#include <cuda_runtime.h>
#include <math.h>
#include <stdint.h>

#define BB 16384

// ---------------- device scratch (static, no allocation) ----------------
__device__ float g_Wcat[128 * 1280];            // [128][1024 MQK | 256 Wres]
__device__ float g_PR[(size_t)BB * 1280];       // per-row: P(1024) | R(256)
__device__ float g_U[(size_t)BB * 1024];        // u per head (4 x 256)
__device__ float g_S[(size_t)BB * 256];         // pre-LN scratch
__device__ float g_Z1[(size_t)BB * 256];
__device__ float g_H1[(size_t)BB * 256];

// ---------------- helpers ----------------
__device__ __forceinline__ float wsum(float v) {
#pragma unroll
  for (int o = 16; o; o >>= 1) v += __shfl_xor_sync(0xffffffffu, v, o);
  return v;
}
__device__ __forceinline__ float wmax(float v) {
#pragma unroll
  for (int o = 16; o; o >>= 1) v = fmaxf(v, __shfl_xor_sync(0xffffffffu, v, o));
  return v;
}

// packed f32x2 FMA: d = a*b + d (elementwise on 2 floats)
#define FMA2(d, a, b) \
  asm("fma.rn.f32x2 %0, %1, %2, %0;" : "+l"(d) : "l"(a), "l"(b))

__device__ __forceinline__ unsigned long long dup2(float x) {
  unsigned long long r;
  asm("mov.b64 %0, {%1, %1};" : "=l"(r) : "f"(x));
  return r;
}
__device__ __forceinline__ float2 unpk(unsigned long long p) {
  float2 r;
  asm("mov.b64 {%0, %1}, %2;" : "=f"(r.x), "=f"(r.y) : "l"(p));
  return r;
}

// bank swizzle for kv rows: XOR bits [2:3] with bits [5:6]; keeps float4 alignment,
// permutes banks within any aligned 32-float window.
__device__ __forceinline__ int SW(int d) {
  return (d & ~31) | ((d & 31) ^ (((d >> 5) & 3) << 2));
}

// FMA-pipe sincos (avoid MUFU.SIN throughput wall). Valid for |z| <~ 1e4.
__device__ __forceinline__ void fast_sincos(float z, float& s, float& c) {
  float t = rintf(z * 0.63661977236758134f);  // 2/pi
  int qi = (int)t;
  float r = fmaf(t, -1.5703125f, z);
  r = fmaf(t, -4.83751296997070312e-4f, r);
  r = fmaf(t, -7.54978995489188e-8f, r);
  float r2 = r * r;
  float sp = fmaf(r2, -1.9515296e-4f, 8.3321608e-3f);
  sp = fmaf(r2, sp, -1.6666654611e-1f);
  float sinr = fmaf(r * r2, sp, r);
  float cp = fmaf(r2, -1.388731625493765e-3f, 4.166664568298827e-2f);
  cp = fmaf(r2, cp, -0.5f);
  float cosr = fmaf(r2, cp, 1.0f);
  int qq = qi & 3;
  float ss = (qq & 1) ? cosr : sinr;
  float cc = (qq & 1) ? sinr : cosr;
  s = (qq & 2) ? -ss : ss;
  c = ((qq + 1) & 2) ? -cc : cc;
}

// ---------------- K0: MQK_h[i][j] = sum_d Wq[i,64h+d]*Wk[j,64h+d] ----------------
__global__ void __launch_bounds__(256) mqk_kernel(const float* __restrict__ Wq,
                                                  const float* __restrict__ Wk) {
  __shared__ float sWq[16 * 68];
  __shared__ float sWk[128 * 68];
  int h = blockIdx.x, is = blockIdx.y;
  int tid = threadIdx.x;
  {
    int il = tid >> 4, d4 = tid & 15;
    *(float4*)&sWq[il * 68 + d4 * 4] =
        *(const float4*)&Wq[(size_t)(is * 16 + il) * 256 + h * 64 + d4 * 4];
  }
  for (int jc = 0; jc < 2; jc++) {
    __syncthreads();
#pragma unroll
    for (int it = 0; it < 8; it++) {
      int f = tid + it * 256;
      int j = f >> 4, d4 = f & 15;
      *(float4*)&sWk[j * 68 + d4 * 4] =
          *(const float4*)&Wk[(size_t)(jc * 128 + j) * 256 + h * 64 + d4 * 4];
    }
    __syncthreads();
    int j = tid & 127, ih = tid >> 7;
#pragma unroll 1
    for (int il = ih * 8; il < ih * 8 + 8; il++) {
      float acc = 0.f;
#pragma unroll
      for (int d = 0; d < 64; d++) acc = fmaf(sWq[il * 68 + d], sWk[j * 68 + d], acc);
      g_Wcat[(size_t)(is * 16 + il) * 1280 + h * 256 + jc * 128 + j] = acc;
    }
  }
}

__global__ void copy_wres_kernel(const float* __restrict__ Wres) {
  int i = blockIdx.x, tid = threadIdx.x;
  g_Wcat[(size_t)i * 1280 + 1024 + tid] = Wres[(size_t)i * 256 + tid];
}

// ---------------- SIMT GEMM, warp tile 16x128, A row-pairs, B dup'd ----------------
// BM=64 BN=256 BK=32, 256 threads. EPI: 0 = store, 1 = relu(x+bias).
template <int EPI>
__global__ void __launch_bounds__(256, 2) gemm_epi(
    const float* __restrict__ A, const float* __restrict__ W, float* __restrict__ C,
    int K, int ldw, int ldc, const float* __restrict__ bias) {
  __shared__ float sAT[32 * 68];   // [kk][row], padded
  __shared__ float sB[32 * 256];
  int tid = threadIdx.x, lane = tid & 31, wid = tid >> 5;
  int rbase = (wid >> 1) * 16;
  int cb = (wid & 1) * 128 + lane * 4;
  int m0 = blockIdx.y * 64, n0 = blockIdx.x * 256;
  unsigned long long acc[8][4];
#pragma unroll
  for (int i = 0; i < 8; i++)
#pragma unroll
    for (int j = 0; j < 4; j++) acc[i][j] = 0ull;

  int kt_n = K >> 5;
  for (int kt = 0; kt < kt_n; kt++) {
    __syncthreads();
#pragma unroll
    for (int it = 0; it < 2; it++) {
      int f = tid + it * 256, r = f >> 3, kq = f & 7;
      float4 v = *(const float4*)&A[(size_t)(m0 + r) * K + kt * 32 + kq * 4];
      sAT[(kq * 4 + 0) * 68 + r] = v.x;
      sAT[(kq * 4 + 1) * 68 + r] = v.y;
      sAT[(kq * 4 + 2) * 68 + r] = v.z;
      sAT[(kq * 4 + 3) * 68 + r] = v.w;
    }
#pragma unroll
    for (int it = 0; it < 8; it++) {
      int f = tid + it * 256, kk = f >> 6, c4 = f & 63;
      *(float4*)&sB[kk * 256 + c4 * 4] =
          *(const float4*)&W[(size_t)(kt * 32 + kk) * ldw + n0 + c4 * 4];
    }
    __syncthreads();
#pragma unroll
    for (int kk = 0; kk < 32; kk++) {
      float4 bv = *(const float4*)&sB[kk * 256 + cb];
      unsigned long long bd0 = dup2(bv.x), bd1 = dup2(bv.y);
      unsigned long long bd2 = dup2(bv.z), bd3 = dup2(bv.w);
      const ulonglong2* ap = (const ulonglong2*)&sAT[kk * 68 + rbase];
      ulonglong2 p0 = ap[0], p1 = ap[1], p2 = ap[2], p3 = ap[3];
      unsigned long long ar[8] = {p0.x, p0.y, p1.x, p1.y, p2.x, p2.y, p3.x, p3.y};
#pragma unroll
      for (int rp = 0; rp < 8; rp++) {
        FMA2(acc[rp][0], ar[rp], bd0);
        FMA2(acc[rp][1], ar[rp], bd1);
        FMA2(acc[rp][2], ar[rp], bd2);
        FMA2(acc[rp][3], ar[rp], bd3);
      }
    }
  }
  // ---- epilogue ----
  float bb[4];
  if (EPI == 1) {
    float4 bv = *(const float4*)&bias[n0 + cb];
    bb[0] = bv.x; bb[1] = bv.y; bb[2] = bv.z; bb[3] = bv.w;
  }
#pragma unroll
  for (int rp = 0; rp < 8; rp++) {
    float2 c0v = unpk(acc[rp][0]);
    float2 c1v = unpk(acc[rp][1]);
    float2 c2v = unpk(acc[rp][2]);
    float2 c3v = unpk(acc[rp][3]);
    float4 o0 = {c0v.x, c1v.x, c2v.x, c3v.x};
    float4 o1 = {c0v.y, c1v.y, c2v.y, c3v.y};
    if (EPI == 1) {
      o0.x = fmaxf(o0.x + bb[0], 0.f); o0.y = fmaxf(o0.y + bb[1], 0.f);
      o0.z = fmaxf(o0.z + bb[2], 0.f); o0.w = fmaxf(o0.w + bb[3], 0.f);
      o1.x = fmaxf(o1.x + bb[0], 0.f); o1.y = fmaxf(o1.y + bb[1], 0.f);
      o1.z = fmaxf(o1.z + bb[2], 0.f); o1.w = fmaxf(o1.w + bb[3], 0.f);
    }
    *(float4*)&C[(size_t)(m0 + rbase + 2 * rp) * ldc + n0 + cb] = o0;
    *(float4*)&C[(size_t)(m0 + rbase + 2 * rp + 1) * ldc + n0 + cb] = o1;
  }
}

// ---------------- K3: head-split GEMM S = u_h @ Wv[:,h*64..] ----------------
// BM=64, BN=256 (4 heads x 64), BK=16, warp tile 16x128, A row-pairs per head.
__global__ void __launch_bounds__(256, 2) gemm_hs(
    const float* __restrict__ Wv, float* __restrict__ C) {
  __shared__ float sAT[16 * 4 * 68];   // [kk][h][row]
  __shared__ float sB[16 * 256];
  int tid = threadIdx.x, lane = tid & 31, wid = tid >> 5;
  int rbase = (wid >> 1) * 16;
  int colslab = wid & 1;
  int cb = colslab * 128 + lane * 4;
  int hl = colslab * 2 + (lane >> 4);
  int m0 = blockIdx.y * 64;
  unsigned long long acc[8][4];
#pragma unroll
  for (int i = 0; i < 8; i++)
#pragma unroll
    for (int j = 0; j < 4; j++) acc[i][j] = 0ull;

  for (int kt = 0; kt < 16; kt++) {
    __syncthreads();
#pragma unroll
    for (int it = 0; it < 4; it++) {
      int f = tid + it * 256;        // 0..1023
      int r = f >> 4, q = f & 15, h = q >> 2, kq = q & 3;
      float4 v = *(const float4*)&g_U[(size_t)(m0 + r) * 1024 + h * 256 +
                                      kt * 16 + kq * 4];
      sAT[((kq * 4 + 0) * 4 + h) * 68 + r] = v.x;
      sAT[((kq * 4 + 1) * 4 + h) * 68 + r] = v.y;
      sAT[((kq * 4 + 2) * 4 + h) * 68 + r] = v.z;
      sAT[((kq * 4 + 3) * 4 + h) * 68 + r] = v.w;
    }
#pragma unroll
    for (int it = 0; it < 4; it++) {
      int f = tid + it * 256, kk = f >> 6, c4 = f & 63;
      *(float4*)&sB[kk * 256 + c4 * 4] =
          *(const float4*)&Wv[(size_t)(kt * 16 + kk) * 256 + c4 * 4];
    }
    __syncthreads();
#pragma unroll
    for (int kk = 0; kk < 16; kk++) {
      float4 bv = *(const float4*)&sB[kk * 256 + cb];
      unsigned long long bd0 = dup2(bv.x), bd1 = dup2(bv.y);
      unsigned long long bd2 = dup2(bv.z), bd3 = dup2(bv.w);
      const ulonglong2* ap = (const ulonglong2*)&sAT[(kk * 4 + hl) * 68 + rbase];
      ulonglong2 p0 = ap[0], p1 = ap[1], p2 = ap[2], p3 = ap[3];
      unsigned long long ar[8] = {p0.x, p0.y, p1.x, p1.y, p2.x, p2.y, p3.x, p3.y};
#pragma unroll
      for (int rp = 0; rp < 8; rp++) {
        FMA2(acc[rp][0], ar[rp], bd0);
        FMA2(acc[rp][1], ar[rp], bd1);
        FMA2(acc[rp][2], ar[rp], bd2);
        FMA2(acc[rp][3], ar[rp], bd3);
      }
    }
  }
#pragma unroll
  for (int rp = 0; rp < 8; rp++) {
    float2 c0v = unpk(acc[rp][0]);
    float2 c1v = unpk(acc[rp][1]);
    float2 c2v = unpk(acc[rp][2]);
    float2 c3v = unpk(acc[rp][3]);
    float4 o0 = {c0v.x, c1v.x, c2v.x, c3v.x};
    float4 o1 = {c0v.y, c1v.y, c2v.y, c3v.y};
    *(float4*)&C[(size_t)(m0 + rbase + 2 * rp) * 256 + cb] = o0;
    *(float4*)&C[(size_t)(m0 + rbase + 2 * rp + 1) * 256 + cb] = o1;
  }
}

// ---------------- K2: attention -> u (swizzled kv, conflict-free STS) ----------
__global__ void __launch_bounds__(256) attn_u_kernel(
    const float* __restrict__ x_ctx, const float* __restrict__ t_ctx,
    const float* __restrict__ freq, const float* __restrict__ phase) {
  __shared__ float kv[32 * 260];
  __shared__ float p2[4 * 8 * 36];
  __shared__ float slog[128];
  __shared__ __align__(16) float sw[128];   // [l][h] packed
  __shared__ float sfr[64], sph[64];
  int b = blockIdx.x, tid = threadIdx.x;
  int l = tid >> 3, sub = tid & 7;

  if (tid < 64) {
    sfr[tid] = freq[tid];
    sph[tid] = phase[tid];
  }
  // repack p: block (h, s2) holds 8 float4 chunks: c0-3 = x dims s2*16..+15,
  // c4-5 = sin dims 128+s2*8..+7, c6-7 = cos dims 192+s2*8..+7
  {
    int h = tid >> 6, r = tid & 63, s2 = r >> 3, c = r & 7;
    int idx4;
    if (c < 4) idx4 = h * 64 + s2 * 4 + c;
    else if (c < 6) idx4 = h * 64 + 32 + s2 * 2 + (c - 4);
    else idx4 = h * 64 + 48 + s2 * 2 + (c - 6);
    float4 v = *(const float4*)&g_PR[(size_t)b * 1280 + (size_t)idx4 * 4];
    *(float4*)&p2[(h * 8 + s2) * 36 + c * 4] = v;
  }
  __syncthreads();

  float acc[4] = {0.f, 0.f, 0.f, 0.f};
  const float* xsrc = x_ctx + ((size_t)b * 32 + l) * 128 + sub * 16;
  float* kvrow = kv + l * 260;

  // x-part: stream 4 chunks: LDG -> swizzled STS -> FMA vs p2
#pragma unroll
  for (int c = 0; c < 4; c++) {
    float4 v = *(const float4*)&xsrc[c * 4];
    *(float4*)&kvrow[SW(sub * 16 + c * 4)] = v;
#pragma unroll
    for (int h = 0; h < 4; h++) {
      float4 p = *(const float4*)&p2[(h * 8 + sub) * 36 + c * 4];
      acc[h] = fmaf(v.x, p.x, acc[h]);
      acc[h] = fmaf(v.y, p.y, acc[h]);
      acc[h] = fmaf(v.z, p.z, acc[h]);
      acc[h] = fmaf(v.w, p.w, acc[h]);
    }
  }
  // te-part
  {
    float t = t_ctx[(size_t)b * 32 + l];
    float lt = log1pf(fmaxf(t, 0.f));
#pragma unroll
    for (int g = 0; g < 2; g++) {
      float4 sv, cv;
      float ss, cc;
      int k0 = sub * 8 + g * 4;
      float z0 = fmaf(lt, sfr[k0 + 0], sph[k0 + 0]);
      float z1 = fmaf(lt, sfr[k0 + 1], sph[k0 + 1]);
      float z2 = fmaf(lt, sfr[k0 + 2], sph[k0 + 2]);
      float z3 = fmaf(lt, sfr[k0 + 3], sph[k0 + 3]);
      fast_sincos(z0, ss, cc); sv.x = ss; cv.x = cc;
      fast_sincos(z1, ss, cc); sv.y = ss; cv.y = cc;
      fast_sincos(z2, ss, cc); sv.z = ss; cv.z = cc;
      fast_sincos(z3, ss, cc); sv.w = ss; cv.w = cc;
      *(float4*)&kvrow[SW(128 + sub * 8 + g * 4)] = sv;
      *(float4*)&kvrow[SW(192 + sub * 8 + g * 4)] = cv;
#pragma unroll
      for (int h = 0; h < 4; h++) {
        float4 ps = *(const float4*)&p2[(h * 8 + sub) * 36 + (4 + g) * 4];
        float4 pc = *(const float4*)&p2[(h * 8 + sub) * 36 + (6 + g) * 4];
        acc[h] = fmaf(sv.x, ps.x, acc[h]);
        acc[h] = fmaf(sv.y, ps.y, acc[h]);
        acc[h] = fmaf(sv.z, ps.z, acc[h]);
        acc[h] = fmaf(sv.w, ps.w, acc[h]);
        acc[h] = fmaf(cv.x, pc.x, acc[h]);
        acc[h] = fmaf(cv.y, pc.y, acc[h]);
        acc[h] = fmaf(cv.z, pc.z, acc[h]);
        acc[h] = fmaf(cv.w, pc.w, acc[h]);
      }
    }
  }
  // reduce over sub (8 lanes)
#pragma unroll
  for (int h = 0; h < 4; h++) {
#pragma unroll
    for (int o = 4; o; o >>= 1) acc[h] += __shfl_xor_sync(0xffffffffu, acc[h], o);
  }
  if (sub < 4) slog[sub * 32 + l] = acc[sub] * 0.125f;
  __syncthreads();
  if (tid < 128) {
    int h = tid >> 5, ll = tid & 31;
    float v = slog[tid];
    float m = wmax(v);
    float e = __expf(v - m);
    float s = wsum(e);
    sw[ll * 4 + h] = e / s;   // packed [l][h]
  }
  __syncthreads();
  // u-phase: thread owns kv-dim j = tid (at swizzled position), all 4 heads.
  {
    int swt = SW(tid);
    unsigned long long a01 = 0ull, a23 = 0ull;
#pragma unroll
    for (int ll = 0; ll < 32; ll++) {
      ulonglong2 w2 = *(const ulonglong2*)&sw[ll * 4];
      unsigned long long vd = dup2(kv[ll * 260 + swt]);
      FMA2(a01, vd, w2.x);
      FMA2(a23, vd, w2.y);
    }
    float2 u01 = unpk(a01);
    float2 u23 = unpk(a23);
    size_t o = (size_t)b * 1024 + tid;
    g_U[o] = u01.x;
    g_U[o + 256] = u01.y;
    g_U[o + 512] = u23.x;
    g_U[o + 768] = u23.y;
  }
}

// ---------------- LN: out = LN(S + resid + bias)*gamma + beta ----------------
__global__ void __launch_bounds__(256) ln_kernel(
    const float* __restrict__ S, const float* __restrict__ resid, int ldres,
    const float* __restrict__ bias, const float* __restrict__ gamma,
    const float* __restrict__ beta, float* __restrict__ out) {
  int row = blockIdx.x * 8 + (threadIdx.x >> 5);
  int lane = threadIdx.x & 31;
  int c0 = lane * 4, c1 = 128 + lane * 4;
  float4 a0 = *(const float4*)&S[(size_t)row * 256 + c0];
  float4 a1 = *(const float4*)&S[(size_t)row * 256 + c1];
  float4 r0 = *(const float4*)&resid[(size_t)row * ldres + c0];
  float4 r1 = *(const float4*)&resid[(size_t)row * ldres + c1];
  float4 b0 = *(const float4*)&bias[c0];
  float4 b1 = *(const float4*)&bias[c1];
  float v[8];
  v[0] = a0.x + r0.x + b0.x;
  v[1] = a0.y + r0.y + b0.y;
  v[2] = a0.z + r0.z + b0.z;
  v[3] = a0.w + r0.w + b0.w;
  v[4] = a1.x + r1.x + b1.x;
  v[5] = a1.y + r1.y + b1.y;
  v[6] = a1.z + r1.z + b1.z;
  v[7] = a1.w + r1.w + b1.w;
  float s = 0.f;
#pragma unroll
  for (int j = 0; j < 8; j++) s += v[j];
  s = wsum(s);
  float mean = s * (1.f / 256.f);
  float q = 0.f;
#pragma unroll
  for (int j = 0; j < 8; j++) {
    float d = v[j] - mean;
    q += d * d;
  }
  q = wsum(q);
  float rstd = rsqrtf(q * (1.f / 256.f) + 1e-5f);
  float4 g0 = *(const float4*)&gamma[c0];
  float4 g1 = *(const float4*)&gamma[c1];
  float4 e0 = *(const float4*)&beta[c0];
  float4 e1 = *(const float4*)&beta[c1];
  float4 o0, o1;
  o0.x = (v[0] - mean) * rstd * g0.x + e0.x;
  o0.y = (v[1] - mean) * rstd * g0.y + e0.y;
  o0.z = (v[2] - mean) * rstd * g0.z + e0.z;
  o0.w = (v[3] - mean) * rstd * g0.w + e0.w;
  o1.x = (v[4] - mean) * rstd * g1.x + e1.x;
  o1.y = (v[5] - mean) * rstd * g1.y + e1.y;
  o1.z = (v[6] - mean) * rstd * g1.z + e1.z;
  o1.w = (v[7] - mean) * rstd * g1.w + e1.w;
  *(float4*)&out[(size_t)row * 256 + c0] = o0;
  *(float4*)&out[(size_t)row * 256 + c1] = o1;
}

// ---------------- launch ----------------
extern "C" void kernel_launch(void* const* d_in, const int* in_sizes, int n_in,
                              void* d_out, int out_size) {
  const float* x_u   = (const float*)d_in[0];
  const float* x_ctx = (const float*)d_in[1];
  const float* t_ctx = (const float*)d_in[2];
  const float* freq  = (const float*)d_in[3];
  const float* phase = (const float*)d_in[4];
  const float* Wq    = (const float*)d_in[5];
  const float* Wk    = (const float*)d_in[6];
  const float* Wv    = (const float*)d_in[7];
  const float* Wres  = (const float*)d_in[8];
  const float* bres  = (const float*)d_in[9];
  const float* W1    = (const float*)d_in[10];
  const float* b1    = (const float*)d_in[11];
  const float* W2    = (const float*)d_in[12];
  const float* b2    = (const float*)d_in[13];
  const float* g1    = (const float*)d_in[14];
  const float* be1   = (const float*)d_in[15];
  const float* g2    = (const float*)d_in[16];
  const float* be2   = (const float*)d_in[17];
  float* out = (float*)d_out;

  float *pWcat, *pPR, *pS, *pZ1, *pH1;
  cudaGetSymbolAddress((void**)&pWcat, g_Wcat);
  cudaGetSymbolAddress((void**)&pPR, g_PR);
  cudaGetSymbolAddress((void**)&pS, g_S);
  cudaGetSymbolAddress((void**)&pZ1, g_Z1);
  cudaGetSymbolAddress((void**)&pH1, g_H1);

  // K0: build [MQK | Wres]
  mqk_kernel<<<dim3(4, 8), 256>>>(Wq, Wk);
  copy_wres_kernel<<<128, 256>>>(Wres);

  // K1: P|R = x_u @ Wcat   [16384,128] x [128,1280]
  gemm_epi<0><<<dim3(5, 256), 256>>>(x_u, pWcat, pPR, 128, 1280, 1280, nullptr);

  // K2: attention -> u
  attn_u_kernel<<<BB, 256>>>(x_ctx, t_ctx, freq, phase);

  // K3: S = u_h @ Wv_h ; z1 = LN(S + R + bres)
  gemm_hs<<<dim3(1, 256), 256>>>(Wv, pS);
  ln_kernel<<<BB / 8, 256>>>(pS, pPR + 1024, 1280, bres, g1, be1, pZ1);

  // K4: h1 = relu(z1 @ W1 + b1)
  gemm_epi<1><<<dim3(1, 256), 256>>>(pZ1, W1, pH1, 256, 256, 256, b1);

  // K5: S = h1 @ W2 ; out = LN(S + z1 + b2)
  gemm_epi<0><<<dim3(1, 256), 256>>>(pH1, W2, pS, 256, 256, 256, nullptr);
  ln_kernel<<<BB / 8, 256>>>(pS, pZ1, 256, b2, g2, be2, out);
}